// round 1
// baseline (speedup 1.0000x reference)
#include <cuda_runtime.h>
#include <math.h>

// ---------------------------------------------------------------------------
// Problem constants (fixed by reference)
// ---------------------------------------------------------------------------
#define DM    1024          // D_MODEL
#define DI    2048          // D_INNER
#define DS    16            // D_STATE
#define DTR   64            // DT_RANK
#define NB    2             // batch
#define LL    2048          // seq len
#define NTOK  (NB*LL)       // 4096 tokens
#define XZC   (2*DI)        // 4096 cols of xz
#define XDBC  (DTR+2*DS)    // 96 cols of xdb

// ---------------------------------------------------------------------------
// Scratch (device globals: no allocation allowed)
// ---------------------------------------------------------------------------
__device__ float g_xn[(size_t)NTOK*DM];       // 16 MB
__device__ float g_xz[(size_t)NTOK*XZC];      // 64 MB  (x_in | z)
__device__ float g_xconv[(size_t)NTOK*DI];    // 32 MB  (silu(conv(x_in)))
__device__ float g_xdb[(size_t)NTOK*XDBC];    // 1.5 MB (dt | B | C)
__device__ float g_delta[(size_t)NTOK*DI];    // 32 MB
__device__ float g_ys[(size_t)NTOK*DI];       // 32 MB

// ---------------------------------------------------------------------------
// LayerNorm: one block per token, 256 threads, 1024 dims
// ---------------------------------------------------------------------------
__global__ void ln_kernel(const float* __restrict__ x, const float* __restrict__ w,
                          const float* __restrict__ bb, float* __restrict__ out)
{
    int t = blockIdx.x;
    const float* xr = x + (size_t)t * DM;
    float v[4];
    float s = 0.f, s2 = 0.f;
#pragma unroll
    for (int i = 0; i < 4; i++) {
        v[i] = xr[threadIdx.x + i * 256];
        s += v[i];
        s2 += v[i] * v[i];
    }
#pragma unroll
    for (int o = 16; o > 0; o >>= 1) {
        s  += __shfl_xor_sync(0xffffffffu, s,  o);
        s2 += __shfl_xor_sync(0xffffffffu, s2, o);
    }
    __shared__ float rs[8], rs2[8];
    int wid = threadIdx.x >> 5, lid = threadIdx.x & 31;
    if (lid == 0) { rs[wid] = s; rs2[wid] = s2; }
    __syncthreads();
    if (wid == 0) {
        float a  = (lid < 8) ? rs[lid]  : 0.f;
        float a2 = (lid < 8) ? rs2[lid] : 0.f;
#pragma unroll
        for (int o = 4; o > 0; o >>= 1) {
            a  += __shfl_xor_sync(0xffffffffu, a,  o);
            a2 += __shfl_xor_sync(0xffffffffu, a2, o);
        }
        if (lid == 0) { rs[0] = a; rs2[0] = a2; }
    }
    __syncthreads();
    float mu   = rs[0] * (1.f / DM);
    float var  = rs2[0] * (1.f / DM) - mu * mu;
    float rstd = rsqrtf(var + 1e-5f);
#pragma unroll
    for (int i = 0; i < 4; i++) {
        int d = threadIdx.x + i * 256;
        out[(size_t)t * DM + d] = (v[i] - mu) * rstd * w[d] + bb[d];
    }
}

// ---------------------------------------------------------------------------
// Generic NT SGEMM: C[M,N] = A[M,K] * B[N,K]^T, both row-major (K-contiguous)
// EPI: 0 = plain store, 1 = softplus(acc + bias[n]), 2 = acc + resid[m,n]
// ---------------------------------------------------------------------------
__device__ __forceinline__ float softplus_f(float v)
{
    return (v > 20.f) ? v : log1pf(expf(v));
}

template<int BM, int BN, int BK, int TM, int TN, int EPI>
__global__ void __launch_bounds__((BM / TM) * (BN / TN))
sgemm_nt(int M, int N, int K,
         const float* __restrict__ A, int lda,
         const float* __restrict__ B, int ldb,
         float* __restrict__ C, int ldc,
         const float* __restrict__ bias,
         const float* __restrict__ resid, int ldr)
{
    constexpr int THREADS = (BM / TM) * (BN / TN);
    constexpr int ASR = BM + 4;   // padded rows (keep 16B alignment: pad %4==0)
    constexpr int BSR = BN + 4;
    __shared__ float Ash[BK][ASR];
    __shared__ float Bsh[BK][BSR];

    const int tid  = threadIdx.x;
    const int bm   = blockIdx.y * BM;
    const int bn   = blockIdx.x * BN;
    const int tcol = tid % (BN / TN);
    const int trow = tid / (BN / TN);

    float acc[TM][TN];
#pragma unroll
    for (int i = 0; i < TM; i++)
#pragma unroll
        for (int j = 0; j < TN; j++) acc[i][j] = 0.f;

    const float* Ab = A + (size_t)bm * lda;
    const float* Bb = B + (size_t)bn * ldb;

    for (int k0 = 0; k0 < K; k0 += BK) {
        for (int i = tid; i < BM * BK; i += THREADS) {
            int m = i / BK, kk = i % BK;
            Ash[kk][m] = Ab[(size_t)m * lda + k0 + kk];
        }
        for (int i = tid; i < BN * BK; i += THREADS) {
            int n = i / BK, kk = i % BK;
            Bsh[kk][n] = Bb[(size_t)n * ldb + k0 + kk];
        }
        __syncthreads();
#pragma unroll
        for (int kk = 0; kk < BK; kk++) {
            float ra[TM], rb[TN];
#pragma unroll
            for (int i = 0; i < TM; i += 4) {
                float4 t4 = *(const float4*)&Ash[kk][trow * TM + i];
                ra[i] = t4.x; ra[i + 1] = t4.y; ra[i + 2] = t4.z; ra[i + 3] = t4.w;
            }
#pragma unroll
            for (int j = 0; j < TN; j += 4) {
                float4 t4 = *(const float4*)&Bsh[kk][tcol * TN + j];
                rb[j] = t4.x; rb[j + 1] = t4.y; rb[j + 2] = t4.z; rb[j + 3] = t4.w;
            }
#pragma unroll
            for (int i = 0; i < TM; i++)
#pragma unroll
                for (int j = 0; j < TN; j++)
                    acc[i][j] = fmaf(ra[i], rb[j], acc[i][j]);
        }
        __syncthreads();
    }

#pragma unroll
    for (int i = 0; i < TM; i++) {
        int m = bm + trow * TM + i;
#pragma unroll
        for (int j = 0; j < TN; j++) {
            int n = bn + tcol * TN + j;
            float v = acc[i][j];
            if (EPI == 1) v = softplus_f(v + bias[n]);
            if (EPI == 2) v += resid[(size_t)m * ldr + n];
            C[(size_t)m * ldc + n] = v;
        }
    }
}

// ---------------------------------------------------------------------------
// Depthwise causal conv (k=4) + bias + SiLU, reading x_in slice of xz
// ---------------------------------------------------------------------------
__global__ void conv_silu_kernel(const float* __restrict__ xz, const float* __restrict__ cw,
                                 const float* __restrict__ cb, float* __restrict__ out)
{
    int idx = blockIdx.x * blockDim.x + threadIdx.x;  // NTOK*DI threads
    int d  = idx & (DI - 1);
    int bt = idx >> 11;        // DI = 2048
    int t  = bt & (LL - 1);
    int b  = bt >> 11;         // LL = 2048

    float w0 = cw[d * 4 + 0], w1 = cw[d * 4 + 1];
    float w2 = cw[d * 4 + 2], w3 = cw[d * 4 + 3];
    const float* col = xz + (size_t)b * LL * XZC + d;  // x_in part, stride XZC
    float acc = cb[d];
    if (t >= 3) acc = fmaf(col[(size_t)(t - 3) * XZC], w0, acc);
    if (t >= 2) acc = fmaf(col[(size_t)(t - 2) * XZC], w1, acc);
    if (t >= 1) acc = fmaf(col[(size_t)(t - 1) * XZC], w2, acc);
    acc = fmaf(col[(size_t)t * XZC], w3, acc);
    float sig = __fdividef(1.f, 1.f + __expf(-acc));
    out[(size_t)bt * DI + d] = acc * sig;
}

// ---------------------------------------------------------------------------
// Selective scan: one thread per (b,d) channel, 16 states in registers.
// Fast path exploits A[d,n] = -(n+1) (verified at runtime): exp(delta*A_n)
// = e^(n+1) with e = expf(-delta) -> 1 MUFU + 15 muls/step instead of 16 MUFU.
// B/C staged in shared in 32-step batches. Fuses + u*D and * silu(z).
// ---------------------------------------------------------------------------
__global__ void __launch_bounds__(128) scan_kernel(
    const float* __restrict__ u, const float* __restrict__ delta,
    const float* __restrict__ xz, const float* __restrict__ xdb,
    const float* __restrict__ A_log, const float* __restrict__ Dp,
    float* __restrict__ ys)
{
    int b = blockIdx.x >> 4;                       // 32 blocks: 2 batches x 16 chunks
    int d = ((blockIdx.x & 15) << 7) + threadIdx.x;

    float An[DS];
    bool fast = true;
#pragma unroll
    for (int n = 0; n < DS; n++) {
        An[n] = -expf(A_log[d * DS + n]);
        fast = fast && (fabsf(An[n] + (float)(n + 1)) < 1e-4f * (float)(n + 1));
    }
    float Dd = Dp[d];
    float h[DS];
#pragma unroll
    for (int n = 0; n < DS; n++) h[n] = 0.f;

    size_t base2  = (size_t)b * LL * DI + d;        // u, delta, ys
    size_t basez  = (size_t)b * LL * XZC + DI + d;  // z slice of xz
    size_t baseBC = (size_t)b * LL * XDBC + DTR;    // B|C in xdb rows

    __shared__ float sBC[32][32];                   // [step][B0..15 | C0..15]

    for (int t0 = 0; t0 < LL; t0 += 32) {
        __syncthreads();
        for (int i = threadIdx.x; i < 1024; i += 128) {
            int tt = i >> 5, j = i & 31;
            sBC[tt][j] = xdb[baseBC + (size_t)(t0 + tt) * XDBC + j];
        }
        __syncthreads();
        for (int s = 0; s < 32; s++) {
            int t = t0 + s;
            float dl = delta[base2 + (size_t)t * DI];
            float ut = u[base2 + (size_t)t * DI];
            float dA[DS];
            if (fast) {
                float e = __expf(-dl);
                float e2 = e * e, e3 = e2 * e, e4 = e2 * e2, e8 = e4 * e4;
                dA[0] = e;        dA[1] = e2;       dA[2] = e3;       dA[3] = e4;
                dA[4] = e4 * e;   dA[5] = e4 * e2;  dA[6] = e4 * e3;  dA[7] = e8;
                dA[8] = e8 * e;   dA[9] = e8 * e2;  dA[10] = e8 * e3; dA[11] = e8 * e4;
                dA[12] = e8 * dA[4]; dA[13] = e8 * dA[5]; dA[14] = e8 * dA[6]; dA[15] = e8 * e8;
            } else {
#pragma unroll
                for (int n = 0; n < DS; n++) dA[n] = __expf(dl * An[n]);
            }
            float w = dl * ut;
            float Bf[DS], Cf[DS];
#pragma unroll
            for (int q = 0; q < 4; q++) {
                float4 bv = *(const float4*)&sBC[s][q * 4];
                Bf[q * 4] = bv.x; Bf[q * 4 + 1] = bv.y; Bf[q * 4 + 2] = bv.z; Bf[q * 4 + 3] = bv.w;
                float4 cv = *(const float4*)&sBC[s][16 + q * 4];
                Cf[q * 4] = cv.x; Cf[q * 4 + 1] = cv.y; Cf[q * 4 + 2] = cv.z; Cf[q * 4 + 3] = cv.w;
            }
#pragma unroll
            for (int n = 0; n < DS; n++)
                h[n] = fmaf(dA[n], h[n], w * Bf[n]);

            float y0 = 0.f, y1 = 0.f, y2 = 0.f, y3 = 0.f;
#pragma unroll
            for (int n = 0; n < DS; n += 4) {
                y0 = fmaf(h[n],     Cf[n],     y0);
                y1 = fmaf(h[n + 1], Cf[n + 1], y1);
                y2 = fmaf(h[n + 2], Cf[n + 2], y2);
                y3 = fmaf(h[n + 3], Cf[n + 3], y3);
            }
            float y  = (y0 + y1) + (y2 + y3) + ut * Dd;
            float zt = xz[basez + (size_t)t * XZC];
            float sig = __fdividef(1.f, 1.f + __expf(-zt));
            ys[base2 + (size_t)t * DI] = y * zt * sig;
        }
    }
}

// ---------------------------------------------------------------------------
// Launch sequence (graph-capturable: kernel launches only)
// ---------------------------------------------------------------------------
extern "C" void kernel_launch(void* const* d_in, const int* in_sizes, int n_in,
                              void* d_out, int out_size)
{
    const float* x         = (const float*)d_in[0];
    const float* norm_w    = (const float*)d_in[1];
    const float* norm_b    = (const float*)d_in[2];
    const float* in_proj_w = (const float*)d_in[3];
    const float* conv_w    = (const float*)d_in[4];
    const float* conv_b    = (const float*)d_in[5];
    const float* x_proj_w  = (const float*)d_in[6];
    const float* dt_proj_w = (const float*)d_in[7];
    const float* dt_proj_b = (const float*)d_in[8];
    const float* A_log     = (const float*)d_in[9];
    const float* D_param   = (const float*)d_in[10];
    const float* out_proj_w= (const float*)d_in[11];
    float* out = (float*)d_out;

    float *xn, *xz, *xconv, *xdb, *deltab, *ysb;
    cudaGetSymbolAddress((void**)&xn,     g_xn);
    cudaGetSymbolAddress((void**)&xz,     g_xz);
    cudaGetSymbolAddress((void**)&xconv,  g_xconv);
    cudaGetSymbolAddress((void**)&xdb,    g_xdb);
    cudaGetSymbolAddress((void**)&deltab, g_delta);
    cudaGetSymbolAddress((void**)&ysb,    g_ys);

    // 1) LayerNorm
    ln_kernel<<<NTOK, 256>>>(x, norm_w, norm_b, xn);

    // 2) in_proj: xz[4096,4096] = xn[4096,1024] @ in_proj_w[4096,1024]^T
    sgemm_nt<128, 128, 16, 8, 8, 0><<<dim3(XZC / 128, NTOK / 128), 256>>>(
        NTOK, XZC, DM, xn, DM, in_proj_w, DM, xz, XZC, nullptr, nullptr, 0);

    // 3) depthwise causal conv + SiLU -> xconv[4096,2048]
    conv_silu_kernel<<<(NTOK * DI) / 256, 256>>>(xz, conv_w, conv_b, xconv);

    // 4) x_proj: xdb[4096,96] = xconv @ x_proj_w[96,2048]^T
    sgemm_nt<128, 32, 16, 8, 4, 0><<<dim3(XDBC / 32, NTOK / 128), 128>>>(
        NTOK, XDBC, DI, xconv, DI, x_proj_w, DI, xdb, XDBC, nullptr, nullptr, 0);

    // 5) dt_proj + bias + softplus: delta[4096,2048] (A = xdb[:, :64], lda = 96)
    sgemm_nt<128, 128, 16, 8, 8, 1><<<dim3(DI / 128, NTOK / 128), 256>>>(
        NTOK, DI, DTR, xdb, XDBC, dt_proj_w, DTR, deltab, DI, dt_proj_b, nullptr, 0);

    // 6) selective scan (fused +u*D and *silu(z)) -> ys[4096,2048]
    scan_kernel<<<32, 128>>>(xconv, deltab, xz, xdb, A_log, D_param, ysb);

    // 7) out_proj + residual: out = x + ys @ out_proj_w[1024,2048]^T
    sgemm_nt<128, 128, 16, 8, 8, 2><<<dim3(DM / 128, NTOK / 128), 256>>>(
        NTOK, DM, DI, ysb, DI, out_proj_w, DI, out, DM, nullptr, x, DM);
}

// round 3
// speedup vs baseline: 1.4457x; 1.4457x over previous
#include <cuda_runtime.h>
#include <cuda_bf16.h>
#include <cstdint>
#include <math.h>

// ---------------------------------------------------------------------------
// Problem constants
// ---------------------------------------------------------------------------
#define DM    1024
#define DI    2048
#define DS    16
#define DTR   64
#define NB    2
#define LL    2048
#define NTOK  (NB*LL)       // 4096
#define XZC   (2*DI)        // 4096
#define XDBC  (DTR+2*DS)    // 96

// ---------------------------------------------------------------------------
// Base-ISA helpers (sm_80+: mma.sync / ldmatrix / cp.async — no 'a' gating)
// ---------------------------------------------------------------------------
__device__ __forceinline__ uint32_t smem_u32(const void* p) {
    uint32_t a;
    asm("{ .reg .u64 t; cvta.to.shared.u64 t, %1; cvt.u32.u64 %0, t; }" : "=r"(a) : "l"(p));
    return a;
}
__device__ __forceinline__ void cp_async16(uint32_t sa, const void* gp) {
    asm volatile("cp.async.cg.shared.global [%0], [%1], 16;" :: "r"(sa), "l"(gp));
}
__device__ __forceinline__ void cp_commit() {
    asm volatile("cp.async.commit_group;" ::: "memory");
}
template<int N>
__device__ __forceinline__ void cp_wait() {
    asm volatile("cp.async.wait_group %0;" :: "n"(N) : "memory");
}
__device__ __forceinline__ void ldsm_x4(uint32_t* r, uint32_t addr) {
    asm volatile("ldmatrix.sync.aligned.m8n8.x4.shared.b16 {%0,%1,%2,%3}, [%4];"
        : "=r"(r[0]), "=r"(r[1]), "=r"(r[2]), "=r"(r[3]) : "r"(addr));
}
__device__ __forceinline__ void ldsm_x2(uint32_t* r, uint32_t addr) {
    asm volatile("ldmatrix.sync.aligned.m8n8.x2.shared.b16 {%0,%1}, [%2];"
        : "=r"(r[0]), "=r"(r[1]) : "r"(addr));
}
__device__ __forceinline__ void mma_bf16(float* c, const uint32_t* a, const uint32_t* b) {
    asm volatile("mma.sync.aligned.m16n8k16.row.col.f32.bf16.bf16.f32 "
        "{%0,%1,%2,%3},{%4,%5,%6,%7},{%8,%9},{%0,%1,%2,%3};"
        : "+f"(c[0]), "+f"(c[1]), "+f"(c[2]), "+f"(c[3])
        : "r"(a[0]), "r"(a[1]), "r"(a[2]), "r"(a[3]), "r"(b[0]), "r"(b[1]));
}
__device__ __forceinline__ void split_bf16(float v, __nv_bfloat16& h, __nv_bfloat16& l) {
    h = __float2bfloat16(v);
    l = __float2bfloat16(v - __bfloat162float(h));
}
__device__ __forceinline__ float softplus_f(float v) {
    return (v > 20.f) ? v : log1pf(expf(v));
}

// ---------------------------------------------------------------------------
// Scratch (device globals)
// ---------------------------------------------------------------------------
__device__ __align__(16) __nv_bfloat16 g_xnh[(size_t)NTOK*DM],  g_xnl[(size_t)NTOK*DM];
__device__ __align__(16) __nv_bfloat16 g_w1h[(size_t)XZC*DM],   g_w1l[(size_t)XZC*DM];
__device__ __align__(16) float         g_xz[(size_t)NTOK*XZC];
__device__ __align__(16) float         g_xconv[(size_t)NTOK*DI];
__device__ __align__(16) __nv_bfloat16 g_xch[(size_t)NTOK*DI],  g_xcl[(size_t)NTOK*DI];
__device__ __align__(16) __nv_bfloat16 g_xpwh[(size_t)XDBC*DI], g_xpwl[(size_t)XDBC*DI];
__device__ __align__(16) float         g_xdb[(size_t)NTOK*XDBC];
__device__ __align__(16) __nv_bfloat16 g_dth[(size_t)NTOK*DTR], g_dtl[(size_t)NTOK*DTR];
__device__ __align__(16) __nv_bfloat16 g_dtwh[(size_t)DI*DTR],  g_dtwl[(size_t)DI*DTR];
__device__ __align__(16) float         g_delta[(size_t)NTOK*DI];
__device__ __align__(16) __nv_bfloat16 g_ysh[(size_t)NTOK*DI],  g_ysl[(size_t)NTOK*DI];
__device__ __align__(16) __nv_bfloat16 g_opwh[(size_t)DM*DI],   g_opwl[(size_t)DM*DI];

// ---------------------------------------------------------------------------
// Weight split f32 -> (hi, lo) bf16
// ---------------------------------------------------------------------------
__global__ void wsplit_kernel(const float* __restrict__ w, __nv_bfloat16* __restrict__ h,
                              __nv_bfloat16* __restrict__ l, int n)
{
    int i = blockIdx.x * 256 + threadIdx.x;
    if (i < n) { __nv_bfloat16 a, b; split_bf16(w[i], a, b); h[i] = a; l[i] = b; }
}

// ---------------------------------------------------------------------------
// LayerNorm -> bf16 hi/lo
// ---------------------------------------------------------------------------
__global__ void ln_kernel(const float* __restrict__ x, const float* __restrict__ w,
                          const float* __restrict__ bb,
                          __nv_bfloat16* __restrict__ oh, __nv_bfloat16* __restrict__ ol)
{
    int t = blockIdx.x;
    const float* xr = x + (size_t)t * DM;
    float v[4];
    float s = 0.f, s2 = 0.f;
#pragma unroll
    for (int i = 0; i < 4; i++) {
        v[i] = xr[threadIdx.x + i * 256];
        s += v[i]; s2 += v[i] * v[i];
    }
#pragma unroll
    for (int o = 16; o > 0; o >>= 1) {
        s  += __shfl_xor_sync(0xffffffffu, s,  o);
        s2 += __shfl_xor_sync(0xffffffffu, s2, o);
    }
    __shared__ float rs[8], rs2[8];
    int wid = threadIdx.x >> 5, lid = threadIdx.x & 31;
    if (lid == 0) { rs[wid] = s; rs2[wid] = s2; }
    __syncthreads();
    if (wid == 0) {
        float a  = (lid < 8) ? rs[lid]  : 0.f;
        float a2 = (lid < 8) ? rs2[lid] : 0.f;
#pragma unroll
        for (int o = 4; o > 0; o >>= 1) {
            a  += __shfl_xor_sync(0xffffffffu, a,  o);
            a2 += __shfl_xor_sync(0xffffffffu, a2, o);
        }
        if (lid == 0) { rs[0] = a; rs2[0] = a2; }
    }
    __syncthreads();
    float mu = rs[0] * (1.f / DM);
    float var = rs2[0] * (1.f / DM) - mu * mu;
    float rstd = rsqrtf(var + 1e-5f);
#pragma unroll
    for (int i = 0; i < 4; i++) {
        int d = threadIdx.x + i * 256;
        float y = (v[i] - mu) * rstd * w[d] + bb[d];
        __nv_bfloat16 hh, llv; split_bf16(y, hh, llv);
        oh[(size_t)t * DM + d] = hh;
        ol[(size_t)t * DM + d] = llv;
    }
}

// ---------------------------------------------------------------------------
// Split-bf16 HMMA GEMM: C[M,N] = A[M,K] @ B[N,K]^T  (fp32 via hi/lo, 3 terms)
// CTA 128 x BN (BN = NWN*32), warp tile 64x32, K-chunks of 32, cp.async
// double-buffered. SMEM rows padded to 80 B (conflict-free ldmatrix).
// EPI: 0 plain, 1 softplus(acc+bias[n]), 2 acc+resid, 3 plain + dt hi/lo split
// ---------------------------------------------------------------------------
template<int NWN, int EPI>
__global__ void __launch_bounds__(64 * NWN, 1) hmma_gemm(
    int M, int N, int K,
    const __nv_bfloat16* __restrict__ Ah, const __nv_bfloat16* __restrict__ Al,
    const __nv_bfloat16* __restrict__ Bh, const __nv_bfloat16* __restrict__ Bl,
    float* __restrict__ C, int ldc,
    const float* __restrict__ bias,
    const float* __restrict__ resid, int ldr,
    __nv_bfloat16* __restrict__ dth, __nv_bfloat16* __restrict__ dtl)
{
    constexpr int BN      = NWN * 32;
    constexpr int THREADS = 64 * NWN;
    constexpr int RSTRIDE = 80;                 // 32 bf16 + 8 pad, bytes
    constexpr int AB      = 128 * RSTRIDE;      // 10240 per term
    constexpr int BB      = BN * RSTRIDE;
    constexpr int BUF     = 2 * AB + 2 * BB;

    extern __shared__ char sm[];
    const uint32_t sbase = smem_u32(sm);

    const int tid  = threadIdx.x;
    const int lane = tid & 31;
    const int wid  = tid >> 5;
    const int warp_m = wid / NWN;               // 0..1
    const int warp_n = wid % NWN;               // 0..NWN-1
    const int bm = blockIdx.y * 128;
    const int bn = blockIdx.x * BN;
    const int KC = K >> 5;                      // chunks of 32

    float acc[4][4][4];
#pragma unroll
    for (int i = 0; i < 4; i++)
#pragma unroll
        for (int j = 0; j < 4; j++)
#pragma unroll
            for (int q = 0; q < 4; q++) acc[i][j][q] = 0.f;

    // chunk loader: chunk c -> buffer b
    auto load_chunk = [&](int c, int b) {
        const int koff = c * 32;
        const uint32_t bbase = sbase + (uint32_t)b * BUF;
        for (int i = tid; i < 1024; i += THREADS) {          // A: 2 terms x 512 units
            int term = i >> 9, j = i & 511;
            int row = j >> 2, seg = j & 3;
            const __nv_bfloat16* gp = (term ? Al : Ah) + (size_t)(bm + row) * K + koff + seg * 8;
            cp_async16(bbase + term * AB + row * RSTRIDE + seg * 16, gp);
        }
        for (int i = tid; i < 2 * BN * 4; i += THREADS) {    // B: 2 terms x BN*4 units
            int term = (i >= BN * 4) ? 1 : 0;
            int j = term ? i - BN * 4 : i;
            int row = j >> 2, seg = j & 3;
            const __nv_bfloat16* gp = (term ? Bl : Bh) + (size_t)(bn + row) * K + koff + seg * 8;
            cp_async16(bbase + 2 * AB + term * BB + row * RSTRIDE + seg * 16, gp);
        }
        cp_commit();
    };

    load_chunk(0, 0);

    for (int c = 0; c < KC; c++) {
        const int b = c & 1;
        if (c + 1 < KC) { load_chunk(c + 1, (c + 1) & 1); cp_wait<1>(); }
        else            { cp_wait<0>(); }
        __syncthreads();

        const uint32_t bbase = sbase + (uint32_t)b * BUF;
#pragma unroll
        for (int ks = 0; ks < 2; ks++) {
            uint32_t ah[4][4], al[4][4], bh[4][2], bl[4][2];
            const uint32_t a_lane = (uint32_t)((warp_m * 64 + (lane & 15)) * RSTRIDE
                                               + ks * 32 + (lane >> 4) * 16);
#pragma unroll
            for (int mi = 0; mi < 4; mi++) {
                ldsm_x4(ah[mi], bbase + a_lane + mi * 16 * RSTRIDE);
                ldsm_x4(al[mi], bbase + AB + a_lane + mi * 16 * RSTRIDE);
            }
            const int l16 = lane & 15;
            const uint32_t b_lane = (uint32_t)((warp_n * 32 + (l16 & 7)) * RSTRIDE
                                               + ks * 32 + (l16 >> 3) * 16);
#pragma unroll
            for (int ni = 0; ni < 4; ni++) {
                ldsm_x2(bh[ni], bbase + 2 * AB + b_lane + ni * 8 * RSTRIDE);
                ldsm_x2(bl[ni], bbase + 2 * AB + BB + b_lane + ni * 8 * RSTRIDE);
            }
#pragma unroll
            for (int mi = 0; mi < 4; mi++)
#pragma unroll
                for (int ni = 0; ni < 4; ni++) {
                    mma_bf16(acc[mi][ni], ah[mi], bh[ni]);
                    mma_bf16(acc[mi][ni], ah[mi], bl[ni]);
                    mma_bf16(acc[mi][ni], al[mi], bh[ni]);
                }
        }
        __syncthreads();
    }

    // epilogue: thread holds (c0,c1)@row, (c2,c3)@row+8, cols n0,n0+1
#pragma unroll
    for (int mi = 0; mi < 4; mi++)
#pragma unroll
        for (int ni = 0; ni < 4; ni++) {
            float* cc = acc[mi][ni];
            const int m0 = bm + warp_m * 64 + mi * 16 + (lane >> 2);
            const int n0 = bn + warp_n * 32 + ni * 8 + (lane & 3) * 2;
#pragma unroll
            for (int half = 0; half < 2; half++) {
                const int m = m0 + half * 8;
                float v0 = cc[half * 2], v1 = cc[half * 2 + 1];
                if (EPI == 1) { v0 = softplus_f(v0 + bias[n0]); v1 = softplus_f(v1 + bias[n0 + 1]); }
                if (EPI == 2) {
                    const float2 r2 = *(const float2*)(resid + (size_t)m * ldr + n0);
                    v0 += r2.x; v1 += r2.y;
                }
                *(float2*)(C + (size_t)m * ldc + n0) = make_float2(v0, v1);
                if (EPI == 3 && n0 < DTR) {
                    __nv_bfloat16 h0, l0, h1, l1;
                    split_bf16(v0, h0, l0); split_bf16(v1, h1, l1);
                    dth[(size_t)m * DTR + n0] = h0; dth[(size_t)m * DTR + n0 + 1] = h1;
                    dtl[(size_t)m * DTR + n0] = l0; dtl[(size_t)m * DTR + n0 + 1] = l1;
                }
            }
        }
}

// ---------------------------------------------------------------------------
// Depthwise causal conv (k=4) + bias + SiLU -> f32 + bf16 hi/lo
// ---------------------------------------------------------------------------
__global__ void conv_silu_kernel(const float* __restrict__ xz, const float* __restrict__ cw,
                                 const float* __restrict__ cb, float* __restrict__ out,
                                 __nv_bfloat16* __restrict__ oh, __nv_bfloat16* __restrict__ ol)
{
    int idx = blockIdx.x * blockDim.x + threadIdx.x;
    int d  = idx & (DI - 1);
    int bt = idx >> 11;
    int t  = bt & (LL - 1);
    int b  = bt >> 11;

    float w0 = cw[d * 4 + 0], w1 = cw[d * 4 + 1];
    float w2 = cw[d * 4 + 2], w3 = cw[d * 4 + 3];
    const float* col = xz + (size_t)b * LL * XZC + d;
    float acc = cb[d];
    if (t >= 3) acc = fmaf(col[(size_t)(t - 3) * XZC], w0, acc);
    if (t >= 2) acc = fmaf(col[(size_t)(t - 2) * XZC], w1, acc);
    if (t >= 1) acc = fmaf(col[(size_t)(t - 1) * XZC], w2, acc);
    acc = fmaf(col[(size_t)t * XZC], w3, acc);
    float sig = __fdividef(1.f, 1.f + __expf(-acc));
    float r = acc * sig;
    out[(size_t)bt * DI + d] = r;
    __nv_bfloat16 hh, llv; split_bf16(r, hh, llv);
    oh[(size_t)bt * DI + d] = hh;
    ol[(size_t)bt * DI + d] = llv;
}

// ---------------------------------------------------------------------------
// Selective scan (thread per channel, fast exp path), writes ys as bf16 hi/lo
// ---------------------------------------------------------------------------
__global__ void __launch_bounds__(128) scan_kernel(
    const float* __restrict__ u, const float* __restrict__ delta,
    const float* __restrict__ xz, const float* __restrict__ xdb,
    const float* __restrict__ A_log, const float* __restrict__ Dp,
    __nv_bfloat16* __restrict__ ysh, __nv_bfloat16* __restrict__ ysl)
{
    int b = blockIdx.x >> 4;
    int d = ((blockIdx.x & 15) << 7) + threadIdx.x;

    float An[DS];
    bool fast = true;
#pragma unroll
    for (int n = 0; n < DS; n++) {
        An[n] = -expf(A_log[d * DS + n]);
        fast = fast && (fabsf(An[n] + (float)(n + 1)) < 1e-4f * (float)(n + 1));
    }
    float Dd = Dp[d];
    float h[DS];
#pragma unroll
    for (int n = 0; n < DS; n++) h[n] = 0.f;

    size_t base2  = (size_t)b * LL * DI + d;
    size_t basez  = (size_t)b * LL * XZC + DI + d;
    size_t baseBC = (size_t)b * LL * XDBC + DTR;

    __shared__ float sBC[32][32];

    for (int t0 = 0; t0 < LL; t0 += 32) {
        __syncthreads();
        for (int i = threadIdx.x; i < 1024; i += 128) {
            int tt = i >> 5, j = i & 31;
            sBC[tt][j] = xdb[baseBC + (size_t)(t0 + tt) * XDBC + j];
        }
        __syncthreads();
        for (int s = 0; s < 32; s++) {
            int t = t0 + s;
            float dl = delta[base2 + (size_t)t * DI];
            float ut = u[base2 + (size_t)t * DI];
            float dA[DS];
            if (fast) {
                float e = __expf(-dl);
                float e2 = e * e, e3 = e2 * e, e4 = e2 * e2, e8 = e4 * e4;
                dA[0] = e;        dA[1] = e2;       dA[2] = e3;       dA[3] = e4;
                dA[4] = e4 * e;   dA[5] = e4 * e2;  dA[6] = e4 * e3;  dA[7] = e8;
                dA[8] = e8 * e;   dA[9] = e8 * e2;  dA[10] = e8 * e3; dA[11] = e8 * e4;
                dA[12] = e8 * dA[4]; dA[13] = e8 * dA[5]; dA[14] = e8 * dA[6]; dA[15] = e8 * e8;
            } else {
#pragma unroll
                for (int n = 0; n < DS; n++) dA[n] = __expf(dl * An[n]);
            }
            float w = dl * ut;
            float Bf[DS], Cf[DS];
#pragma unroll
            for (int q = 0; q < 4; q++) {
                float4 bv = *(const float4*)&sBC[s][q * 4];
                Bf[q*4] = bv.x; Bf[q*4+1] = bv.y; Bf[q*4+2] = bv.z; Bf[q*4+3] = bv.w;
                float4 cv = *(const float4*)&sBC[s][16 + q * 4];
                Cf[q*4] = cv.x; Cf[q*4+1] = cv.y; Cf[q*4+2] = cv.z; Cf[q*4+3] = cv.w;
            }
#pragma unroll
            for (int n = 0; n < DS; n++)
                h[n] = fmaf(dA[n], h[n], w * Bf[n]);

            float y0 = 0.f, y1 = 0.f, y2 = 0.f, y3 = 0.f;
#pragma unroll
            for (int n = 0; n < DS; n += 4) {
                y0 = fmaf(h[n],     Cf[n],     y0);
                y1 = fmaf(h[n + 1], Cf[n + 1], y1);
                y2 = fmaf(h[n + 2], Cf[n + 2], y2);
                y3 = fmaf(h[n + 3], Cf[n + 3], y3);
            }
            float y  = (y0 + y1) + (y2 + y3) + ut * Dd;
            float zt = xz[basez + (size_t)t * XZC];
            float sig = __fdividef(1.f, 1.f + __expf(-zt));
            float r = y * zt * sig;
            __nv_bfloat16 hh, llv; split_bf16(r, hh, llv);
            ysh[base2 + (size_t)t * DI] = hh;
            ysl[base2 + (size_t)t * DI] = llv;
        }
    }
}

// ---------------------------------------------------------------------------
// Launch sequence
// ---------------------------------------------------------------------------
static inline int gemm_smem(int BN) { return 2 * (2 * 128 * 80 + 2 * BN * 80); }

extern "C" void kernel_launch(void* const* d_in, const int* in_sizes, int n_in,
                              void* d_out, int out_size)
{
    const float* x         = (const float*)d_in[0];
    const float* norm_w    = (const float*)d_in[1];
    const float* norm_b    = (const float*)d_in[2];
    const float* in_proj_w = (const float*)d_in[3];
    const float* conv_w    = (const float*)d_in[4];
    const float* conv_b    = (const float*)d_in[5];
    const float* x_proj_w  = (const float*)d_in[6];
    const float* dt_proj_w = (const float*)d_in[7];
    const float* dt_proj_b = (const float*)d_in[8];
    const float* A_log     = (const float*)d_in[9];
    const float* D_param   = (const float*)d_in[10];
    const float* out_proj_w= (const float*)d_in[11];
    float* out = (float*)d_out;

    __nv_bfloat16 *xnh, *xnl, *w1h, *w1l, *xch, *xcl, *xpwh, *xpwl;
    __nv_bfloat16 *dth, *dtl, *dtwh, *dtwl, *ysh, *ysl, *opwh, *opwl;
    float *xz, *xconv, *xdb, *deltab;
    cudaGetSymbolAddress((void**)&xnh, g_xnh);   cudaGetSymbolAddress((void**)&xnl, g_xnl);
    cudaGetSymbolAddress((void**)&w1h, g_w1h);   cudaGetSymbolAddress((void**)&w1l, g_w1l);
    cudaGetSymbolAddress((void**)&xz, g_xz);     cudaGetSymbolAddress((void**)&xconv, g_xconv);
    cudaGetSymbolAddress((void**)&xch, g_xch);   cudaGetSymbolAddress((void**)&xcl, g_xcl);
    cudaGetSymbolAddress((void**)&xpwh, g_xpwh); cudaGetSymbolAddress((void**)&xpwl, g_xpwl);
    cudaGetSymbolAddress((void**)&xdb, g_xdb);
    cudaGetSymbolAddress((void**)&dth, g_dth);   cudaGetSymbolAddress((void**)&dtl, g_dtl);
    cudaGetSymbolAddress((void**)&dtwh, g_dtwh); cudaGetSymbolAddress((void**)&dtwl, g_dtwl);
    cudaGetSymbolAddress((void**)&deltab, g_delta);
    cudaGetSymbolAddress((void**)&ysh, g_ysh);   cudaGetSymbolAddress((void**)&ysl, g_ysl);
    cudaGetSymbolAddress((void**)&opwh, g_opwh); cudaGetSymbolAddress((void**)&opwl, g_opwl);

    cudaFuncSetAttribute(hmma_gemm<4, 0>, cudaFuncAttributeMaxDynamicSharedMemorySize, gemm_smem(128));
    cudaFuncSetAttribute(hmma_gemm<4, 1>, cudaFuncAttributeMaxDynamicSharedMemorySize, gemm_smem(128));
    cudaFuncSetAttribute(hmma_gemm<4, 2>, cudaFuncAttributeMaxDynamicSharedMemorySize, gemm_smem(128));
    cudaFuncSetAttribute(hmma_gemm<3, 3>, cudaFuncAttributeMaxDynamicSharedMemorySize, gemm_smem(96));

    // weight splits
    wsplit_kernel<<<(XZC * DM + 255) / 256, 256>>>(in_proj_w, w1h, w1l, XZC * DM);
    wsplit_kernel<<<(XDBC * DI + 255) / 256, 256>>>(x_proj_w, xpwh, xpwl, XDBC * DI);
    wsplit_kernel<<<(DI * DTR + 255) / 256, 256>>>(dt_proj_w, dtwh, dtwl, DI * DTR);
    wsplit_kernel<<<(DM * DI + 255) / 256, 256>>>(out_proj_w, opwh, opwl, DM * DI);

    // 1) LayerNorm -> xn hi/lo
    ln_kernel<<<NTOK, 256>>>(x, norm_w, norm_b, xnh, xnl);

    // 2) in_proj: xz[4096,4096] = xn @ in_proj_w^T
    hmma_gemm<4, 0><<<dim3(XZC / 128, NTOK / 128), 256, gemm_smem(128)>>>(
        NTOK, XZC, DM, xnh, xnl, w1h, w1l, xz, XZC, nullptr, nullptr, 0, nullptr, nullptr);

    // 3) conv + SiLU -> xconv f32 + hi/lo
    conv_silu_kernel<<<(NTOK * DI) / 256, 256>>>(xz, conv_w, conv_b, xconv, xch, xcl);

    // 4) x_proj: xdb[4096,96] = xconv @ x_proj_w^T (+ dt hi/lo split)
    hmma_gemm<3, 3><<<dim3(1, NTOK / 128), 192, gemm_smem(96)>>>(
        NTOK, XDBC, DI, xch, xcl, xpwh, xpwl, xdb, XDBC, nullptr, nullptr, 0, dth, dtl);

    // 5) dt_proj + softplus: delta[4096,2048]
    hmma_gemm<4, 1><<<dim3(DI / 128, NTOK / 128), 256, gemm_smem(128)>>>(
        NTOK, DI, DTR, dth, dtl, dtwh, dtwl, deltab, DI, dt_proj_b, nullptr, 0, nullptr, nullptr);

    // 6) selective scan -> ys hi/lo
    scan_kernel<<<32, 128>>>(xconv, deltab, xz, xdb, A_log, D_param, ysh, ysl);

    // 7) out_proj + residual
    hmma_gemm<4, 2><<<dim3(DM / 128, NTOK / 128), 256, gemm_smem(128)>>>(
        NTOK, DM, DI, ysh, ysl, opwh, opwl, out, DM, nullptr, x, DM, nullptr, nullptr);
}

// round 5
// speedup vs baseline: 6.2556x; 4.3269x over previous
#include <cuda_runtime.h>
#include <cuda_fp16.h>
#include <cstdint>
#include <math.h>

// ---------------------------------------------------------------------------
// Problem constants
// ---------------------------------------------------------------------------
#define DM    1024
#define DI    2048
#define DS    16
#define DTR   64
#define NB    2
#define LL    2048
#define NTOK  (NB*LL)       // 4096
#define XZC   (2*DI)        // 4096
#define XDBC  (DTR+2*DS)    // 96
#define XPS   4             // x_proj split-K factor

// ---------------------------------------------------------------------------
// Base-ISA helpers (sm_80+; no 'a'-gated instructions)
// ---------------------------------------------------------------------------
__device__ __forceinline__ uint32_t smem_u32(const void* p) {
    uint32_t a;
    asm("{ .reg .u64 t; cvta.to.shared.u64 t, %1; cvt.u32.u64 %0, t; }" : "=r"(a) : "l"(p));
    return a;
}
__device__ __forceinline__ void cp_async16(uint32_t sa, const void* gp) {
    asm volatile("cp.async.cg.shared.global [%0], [%1], 16;" :: "r"(sa), "l"(gp));
}
__device__ __forceinline__ void cp_commit() {
    asm volatile("cp.async.commit_group;" ::: "memory");
}
template<int N>
__device__ __forceinline__ void cp_wait() {
    asm volatile("cp.async.wait_group %0;" :: "n"(N) : "memory");
}
__device__ __forceinline__ void ldsm_x4(uint32_t* r, uint32_t addr) {
    asm volatile("ldmatrix.sync.aligned.m8n8.x4.shared.b16 {%0,%1,%2,%3}, [%4];"
        : "=r"(r[0]), "=r"(r[1]), "=r"(r[2]), "=r"(r[3]) : "r"(addr));
}
__device__ __forceinline__ void ldsm_x2(uint32_t* r, uint32_t addr) {
    asm volatile("ldmatrix.sync.aligned.m8n8.x2.shared.b16 {%0,%1}, [%2];"
        : "=r"(r[0]), "=r"(r[1]) : "r"(addr));
}
__device__ __forceinline__ void mma_fp16(float* c, const uint32_t* a, const uint32_t* b) {
    asm volatile("mma.sync.aligned.m16n8k16.row.col.f32.f16.f16.f32 "
        "{%0,%1,%2,%3},{%4,%5,%6,%7},{%8,%9},{%0,%1,%2,%3};"
        : "+f"(c[0]), "+f"(c[1]), "+f"(c[2]), "+f"(c[3])
        : "r"(a[0]), "r"(a[1]), "r"(a[2]), "r"(a[3]), "r"(b[0]), "r"(b[1]));
}
__device__ __forceinline__ float softplus_f(float v) {
    return (v > 20.f) ? v : log1pf(expf(v));
}

// ---------------------------------------------------------------------------
// Scratch (device globals)
// ---------------------------------------------------------------------------
__device__ __align__(16) __half g_xnh[(size_t)NTOK*DM];
__device__ __align__(16) __half g_w1h[(size_t)XZC*DM];
__device__ __align__(16) float  g_xz[(size_t)NTOK*XZC];
__device__ __align__(16) float  g_xconv[(size_t)NTOK*DI];
__device__ __align__(16) __half g_xch[(size_t)NTOK*DI];
__device__ __align__(16) __half g_xpwh[(size_t)XDBC*DI];
__device__ __align__(16) float  g_xdbp[(size_t)XPS*NTOK*XDBC];  // split-K partials
__device__ __align__(16) float  g_xdb[(size_t)NTOK*XDBC];
__device__ __align__(16) __half g_dth[(size_t)NTOK*DTR];
__device__ __align__(16) __half g_dtwh[(size_t)DI*DTR];
__device__ __align__(16) float  g_delta[(size_t)NTOK*DI];
__device__ __align__(16) __half g_ysh[(size_t)NTOK*DI];
__device__ __align__(16) __half g_opwh[(size_t)DM*DI];

// ---------------------------------------------------------------------------
// f32 -> fp16 convert
// ---------------------------------------------------------------------------
__global__ void whalf_kernel(const float* __restrict__ w, __half* __restrict__ h, int n)
{
    int i = blockIdx.x * 256 + threadIdx.x;
    if (i < n) h[i] = __float2half_rn(w[i]);
}

// ---------------------------------------------------------------------------
// LayerNorm -> fp16
// ---------------------------------------------------------------------------
__global__ void ln_kernel(const float* __restrict__ x, const float* __restrict__ w,
                          const float* __restrict__ bb, __half* __restrict__ oh)
{
    int t = blockIdx.x;
    const float* xr = x + (size_t)t * DM;
    float v[4];
    float s = 0.f, s2 = 0.f;
#pragma unroll
    for (int i = 0; i < 4; i++) {
        v[i] = xr[threadIdx.x + i * 256];
        s += v[i]; s2 += v[i] * v[i];
    }
#pragma unroll
    for (int o = 16; o > 0; o >>= 1) {
        s  += __shfl_xor_sync(0xffffffffu, s,  o);
        s2 += __shfl_xor_sync(0xffffffffu, s2, o);
    }
    __shared__ float rs[8], rs2[8];
    int wid = threadIdx.x >> 5, lid = threadIdx.x & 31;
    if (lid == 0) { rs[wid] = s; rs2[wid] = s2; }
    __syncthreads();
    if (wid == 0) {
        float a  = (lid < 8) ? rs[lid]  : 0.f;
        float a2 = (lid < 8) ? rs2[lid] : 0.f;
#pragma unroll
        for (int o = 4; o > 0; o >>= 1) {
            a  += __shfl_xor_sync(0xffffffffu, a,  o);
            a2 += __shfl_xor_sync(0xffffffffu, a2, o);
        }
        if (lid == 0) { rs[0] = a; rs2[0] = a2; }
    }
    __syncthreads();
    float mu = rs[0] * (1.f / DM);
    float var = rs2[0] * (1.f / DM) - mu * mu;
    float rstd = rsqrtf(var + 1e-5f);
#pragma unroll
    for (int i = 0; i < 4; i++) {
        int d = threadIdx.x + i * 256;
        float y = (v[i] - mu) * rstd * w[d] + bb[d];
        oh[(size_t)t * DM + d] = __float2half_rn(y);
    }
}

// ---------------------------------------------------------------------------
// fp16 HMMA GEMM: C[M,N] = A[M,K] @ B[N,K]^T, f32 accum.
// CTA 128 x BN (BN = NWN*32), warp tile 64x32, K-chunks of 32, cp.async
// double-buffered, SMEM rows padded to 80 B. Optional split-K over gridDim.z
// (each z handles Kper, writes to C + z*M*ldc).
// EPI: 0 plain, 1 softplus(acc+bias[n]), 2 acc+resid
// ---------------------------------------------------------------------------
template<int NWN, int EPI>
__global__ void __launch_bounds__(64 * NWN) hmma_gemm(
    int M, int N, int Ktot, int Kper,
    const __half* __restrict__ A, const __half* __restrict__ B,
    float* __restrict__ C, int ldc,
    const float* __restrict__ bias,
    const float* __restrict__ resid, int ldr)
{
    constexpr int BN      = NWN * 32;
    constexpr int THREADS = 64 * NWN;
    constexpr int RSTRIDE = 80;                 // 32 fp16 (64B) + 16 pad
    constexpr int AB      = 128 * RSTRIDE;
    constexpr int BB      = BN * RSTRIDE;
    constexpr int BUF     = AB + BB;

    extern __shared__ char smraw[];
    const uint32_t sbase = smem_u32(smraw);

    const int tid  = threadIdx.x;
    const int lane = tid & 31;
    const int wid  = tid >> 5;
    const int warp_m = wid / NWN;
    const int warp_n = wid % NWN;
    const int bm = blockIdx.y * 128;
    const int bn = blockIdx.x * BN;
    const int kbase = blockIdx.z * Kper;
    const int KC = Kper >> 5;
    float* Cz = C + (size_t)blockIdx.z * M * ldc;

    float acc[4][4][4];
#pragma unroll
    for (int i = 0; i < 4; i++)
#pragma unroll
        for (int j = 0; j < 4; j++)
#pragma unroll
            for (int q = 0; q < 4; q++) acc[i][j][q] = 0.f;

    auto load_chunk = [&](int c, int b) {
        const int koff = kbase + c * 32;
        const uint32_t bbase = sbase + (uint32_t)b * BUF;
        for (int i = tid; i < 512; i += THREADS) {           // A: 128 rows x 4 segs
            int row = i >> 2, seg = i & 3;
            cp_async16(bbase + row * RSTRIDE + seg * 16,
                       A + (size_t)(bm + row) * Ktot + koff + seg * 8);
        }
        for (int i = tid; i < BN * 4; i += THREADS) {        // B: BN rows x 4 segs
            int row = i >> 2, seg = i & 3;
            cp_async16(bbase + AB + row * RSTRIDE + seg * 16,
                       B + (size_t)(bn + row) * Ktot + koff + seg * 8);
        }
        cp_commit();
    };

    load_chunk(0, 0);

    for (int c = 0; c < KC; c++) {
        const int b = c & 1;
        if (c + 1 < KC) { load_chunk(c + 1, (c + 1) & 1); cp_wait<1>(); }
        else            { cp_wait<0>(); }
        __syncthreads();

        const uint32_t bbase = sbase + (uint32_t)b * BUF;
#pragma unroll
        for (int ks = 0; ks < 2; ks++) {
            uint32_t ah[4][4], bh[4][2];
            const uint32_t a_lane = (uint32_t)((warp_m * 64 + (lane & 15)) * RSTRIDE
                                               + ks * 32 + (lane >> 4) * 16);
#pragma unroll
            for (int mi = 0; mi < 4; mi++)
                ldsm_x4(ah[mi], bbase + a_lane + mi * 16 * RSTRIDE);
            const int l16 = lane & 15;
            const uint32_t b_lane = (uint32_t)((warp_n * 32 + (l16 & 7)) * RSTRIDE
                                               + ks * 32 + (l16 >> 3) * 16);
#pragma unroll
            for (int ni = 0; ni < 4; ni++)
                ldsm_x2(bh[ni], bbase + AB + b_lane + ni * 8 * RSTRIDE);
#pragma unroll
            for (int mi = 0; mi < 4; mi++)
#pragma unroll
                for (int ni = 0; ni < 4; ni++)
                    mma_fp16(acc[mi][ni], ah[mi], bh[ni]);
        }
        __syncthreads();
    }

#pragma unroll
    for (int mi = 0; mi < 4; mi++)
#pragma unroll
        for (int ni = 0; ni < 4; ni++) {
            float* cc = acc[mi][ni];
            const int m0 = bm + warp_m * 64 + mi * 16 + (lane >> 2);
            const int n0 = bn + warp_n * 32 + ni * 8 + (lane & 3) * 2;
#pragma unroll
            for (int half = 0; half < 2; half++) {
                const int m = m0 + half * 8;
                float v0 = cc[half * 2], v1 = cc[half * 2 + 1];
                if (EPI == 1) { v0 = softplus_f(v0 + bias[n0]); v1 = softplus_f(v1 + bias[n0 + 1]); }
                if (EPI == 2) {
                    const float2 r2 = *(const float2*)(resid + (size_t)m * ldr + n0);
                    v0 += r2.x; v1 += r2.y;
                }
                *(float2*)(Cz + (size_t)m * ldc + n0) = make_float2(v0, v1);
            }
        }
}

// ---------------------------------------------------------------------------
// x_proj split-K reduce: xdb = sum_z partials; also emit dt (cols 0..63) fp16
// ---------------------------------------------------------------------------
__global__ void xdb_reduce_kernel(const float* __restrict__ part, float* __restrict__ xdb,
                                  __half* __restrict__ dth)
{
    int idx = blockIdx.x * 256 + threadIdx.x;
    if (idx >= NTOK * XDBC) return;
    float s = 0.f;
#pragma unroll
    for (int z = 0; z < XPS; z++) s += part[(size_t)z * NTOK * XDBC + idx];
    xdb[idx] = s;
    int n = idx % XDBC;
    if (n < DTR) {
        int m = idx / XDBC;
        dth[(size_t)m * DTR + n] = __float2half_rn(s);
    }
}

// ---------------------------------------------------------------------------
// Depthwise causal conv (k=4) + bias + SiLU -> f32 + fp16
// ---------------------------------------------------------------------------
__global__ void conv_silu_kernel(const float* __restrict__ xz, const float* __restrict__ cw,
                                 const float* __restrict__ cb, float* __restrict__ out,
                                 __half* __restrict__ oh)
{
    int idx = blockIdx.x * blockDim.x + threadIdx.x;
    int d  = idx & (DI - 1);
    int bt = idx >> 11;
    int t  = bt & (LL - 1);
    int b  = bt >> 11;

    float w0 = cw[d * 4 + 0], w1 = cw[d * 4 + 1];
    float w2 = cw[d * 4 + 2], w3 = cw[d * 4 + 3];
    const float* col = xz + (size_t)b * LL * XZC + d;
    float acc = cb[d];
    if (t >= 3) acc = fmaf(col[(size_t)(t - 3) * XZC], w0, acc);
    if (t >= 2) acc = fmaf(col[(size_t)(t - 2) * XZC], w1, acc);
    if (t >= 1) acc = fmaf(col[(size_t)(t - 1) * XZC], w2, acc);
    acc = fmaf(col[(size_t)t * XZC], w3, acc);
    float sig = __fdividef(1.f, 1.f + __expf(-acc));
    float r = acc * sig;
    out[(size_t)bt * DI + d] = r;
    oh[(size_t)bt * DI + d] = __float2half_rn(r);
}

// ---------------------------------------------------------------------------
// Selective scan. Tiles of 32 steps; u/delta/z/BC staged to shared via
// cp.async (double buffered) so the serial chain never touches DRAM latency.
// Per-buffer floats: U[32][128] D[32][128] Z[32][128] BC[32][32] = 13312.
// ---------------------------------------------------------------------------
#define SCAN_TILEF 13312
__global__ void __launch_bounds__(128) scan_kernel(
    const float* __restrict__ u, const float* __restrict__ delta,
    const float* __restrict__ xz, const float* __restrict__ xdb,
    const float* __restrict__ A_log, const float* __restrict__ Dp,
    __half* __restrict__ ysh)
{
    extern __shared__ char smraw[];
    float* sm = (float*)smraw;
    const uint32_t sbase = smem_u32(smraw);
    const int tid = threadIdx.x;
    const int b = blockIdx.x >> 4;
    const int d0 = (blockIdx.x & 15) << 7;
    const int d = d0 + tid;

    float An[DS];
    bool fast = true;
#pragma unroll
    for (int n = 0; n < DS; n++) {
        An[n] = -expf(A_log[d * DS + n]);
        fast = fast && (fabsf(An[n] + (float)(n + 1)) < 1e-4f * (float)(n + 1));
    }
    float Dd = Dp[d];
    float h[DS];
#pragma unroll
    for (int n = 0; n < DS; n++) h[n] = 0.f;

    const size_t base_u  = (size_t)b * LL * DI + d0;        // + t*DI
    const size_t base_z  = (size_t)b * LL * XZC + DI + d0;  // + t*XZC
    const size_t base_bc = (size_t)b * LL * XDBC + DTR;     // + t*XDBC

    auto load_tile = [&](int t0, int buf) {
        const uint32_t db = sbase + (uint32_t)buf * (SCAN_TILEF * 4u);
        for (int i = tid; i < 3072; i += 128) {
            int arr = i >> 10;
            int j = i & 1023;
            int s = j >> 5, q = (j & 31) * 4;
            const float* gp;
            if (arr == 0)      gp = u     + base_u + (size_t)(t0 + s) * DI  + q;
            else if (arr == 1) gp = delta + base_u + (size_t)(t0 + s) * DI  + q;
            else               gp = xz    + base_z + (size_t)(t0 + s) * XZC + q;
            cp_async16(db + (uint32_t)(arr * 4096 + s * 128 + q) * 4u, gp);
        }
        for (int i = tid; i < 256; i += 128) {
            int s = i >> 3, q = (i & 7) * 4;
            cp_async16(db + (uint32_t)(12288 + s * 32 + q) * 4u,
                       xdb + base_bc + (size_t)(t0 + s) * XDBC + q);
        }
        cp_commit();
    };

    load_tile(0, 0);

    for (int t0 = 0; t0 < LL; t0 += 32) {
        const int buf = (t0 >> 5) & 1;
        if (t0 + 32 < LL) { load_tile(t0 + 32, buf ^ 1); cp_wait<1>(); }
        else              { cp_wait<0>(); }
        __syncthreads();

        const float* sU  = sm + buf * SCAN_TILEF;
        const float* sD  = sU + 4096;
        const float* sZ  = sU + 8192;
        const float* sBC = sU + 12288;

        for (int s = 0; s < 32; s++) {
            float dl = sD[s * 128 + tid];
            float ut = sU[s * 128 + tid];
            float dA[DS];
            if (fast) {
                float e = __expf(-dl);
                float e2 = e * e, e3 = e2 * e, e4 = e2 * e2, e8 = e4 * e4;
                dA[0] = e;        dA[1] = e2;       dA[2] = e3;       dA[3] = e4;
                dA[4] = e4 * e;   dA[5] = e4 * e2;  dA[6] = e4 * e3;  dA[7] = e8;
                dA[8] = e8 * e;   dA[9] = e8 * e2;  dA[10] = e8 * e3; dA[11] = e8 * e4;
                dA[12] = e8 * dA[4]; dA[13] = e8 * dA[5]; dA[14] = e8 * dA[6]; dA[15] = e8 * e8;
            } else {
#pragma unroll
                for (int n = 0; n < DS; n++) dA[n] = __expf(dl * An[n]);
            }
            float w = dl * ut;
            float Bf[DS], Cf[DS];
#pragma unroll
            for (int q = 0; q < 4; q++) {
                float4 bv = *(const float4*)&sBC[s * 32 + q * 4];
                Bf[q*4] = bv.x; Bf[q*4+1] = bv.y; Bf[q*4+2] = bv.z; Bf[q*4+3] = bv.w;
                float4 cv = *(const float4*)&sBC[s * 32 + 16 + q * 4];
                Cf[q*4] = cv.x; Cf[q*4+1] = cv.y; Cf[q*4+2] = cv.z; Cf[q*4+3] = cv.w;
            }
#pragma unroll
            for (int n = 0; n < DS; n++)
                h[n] = fmaf(dA[n], h[n], w * Bf[n]);

            float y0 = 0.f, y1 = 0.f, y2 = 0.f, y3 = 0.f;
#pragma unroll
            for (int n = 0; n < DS; n += 4) {
                y0 = fmaf(h[n],     Cf[n],     y0);
                y1 = fmaf(h[n + 1], Cf[n + 1], y1);
                y2 = fmaf(h[n + 2], Cf[n + 2], y2);
                y3 = fmaf(h[n + 3], Cf[n + 3], y3);
            }
            float y  = (y0 + y1) + (y2 + y3) + ut * Dd;
            float zt = sZ[s * 128 + tid];
            float sig = __fdividef(1.f, 1.f + __expf(-zt));
            ysh[base_u + (size_t)(t0 + s) * DI + tid] = __float2half_rn(y * zt * sig);
        }
        __syncthreads();
    }
}

// ---------------------------------------------------------------------------
// Launch sequence
// ---------------------------------------------------------------------------
static inline int gemm_smem(int BN) { return 2 * (128 + BN) * 80; }

extern "C" void kernel_launch(void* const* d_in, const int* in_sizes, int n_in,
                              void* d_out, int out_size)
{
    const float* x         = (const float*)d_in[0];
    const float* norm_w    = (const float*)d_in[1];
    const float* norm_b    = (const float*)d_in[2];
    const float* in_proj_w = (const float*)d_in[3];
    const float* conv_w    = (const float*)d_in[4];
    const float* conv_b    = (const float*)d_in[5];
    const float* x_proj_w  = (const float*)d_in[6];
    const float* dt_proj_w = (const float*)d_in[7];
    const float* dt_proj_b = (const float*)d_in[8];
    const float* A_log     = (const float*)d_in[9];
    const float* D_param   = (const float*)d_in[10];
    const float* out_proj_w= (const float*)d_in[11];
    float* out = (float*)d_out;

    __half *xnh, *w1h, *xch, *xpwh, *dth, *dtwh, *ysh, *opwh;
    float *xz, *xconv, *xdbp, *xdb, *deltab;
    cudaGetSymbolAddress((void**)&xnh, g_xnh);
    cudaGetSymbolAddress((void**)&w1h, g_w1h);
    cudaGetSymbolAddress((void**)&xz, g_xz);
    cudaGetSymbolAddress((void**)&xconv, g_xconv);
    cudaGetSymbolAddress((void**)&xch, g_xch);
    cudaGetSymbolAddress((void**)&xpwh, g_xpwh);
    cudaGetSymbolAddress((void**)&xdbp, g_xdbp);
    cudaGetSymbolAddress((void**)&xdb, g_xdb);
    cudaGetSymbolAddress((void**)&dth, g_dth);
    cudaGetSymbolAddress((void**)&dtwh, g_dtwh);
    cudaGetSymbolAddress((void**)&deltab, g_delta);
    cudaGetSymbolAddress((void**)&ysh, g_ysh);
    cudaGetSymbolAddress((void**)&opwh, g_opwh);

    cudaFuncSetAttribute(hmma_gemm<4, 0>, cudaFuncAttributeMaxDynamicSharedMemorySize, gemm_smem(128));
    cudaFuncSetAttribute(hmma_gemm<4, 1>, cudaFuncAttributeMaxDynamicSharedMemorySize, gemm_smem(128));
    cudaFuncSetAttribute(hmma_gemm<4, 2>, cudaFuncAttributeMaxDynamicSharedMemorySize, gemm_smem(128));
    cudaFuncSetAttribute(hmma_gemm<3, 0>, cudaFuncAttributeMaxDynamicSharedMemorySize, gemm_smem(96));
    cudaFuncSetAttribute(scan_kernel, cudaFuncAttributeMaxDynamicSharedMemorySize, 2 * SCAN_TILEF * 4);

    // weight converts
    whalf_kernel<<<(XZC * DM + 255) / 256, 256>>>(in_proj_w, w1h, XZC * DM);
    whalf_kernel<<<(XDBC * DI + 255) / 256, 256>>>(x_proj_w, xpwh, XDBC * DI);
    whalf_kernel<<<(DI * DTR + 255) / 256, 256>>>(dt_proj_w, dtwh, DI * DTR);
    whalf_kernel<<<(DM * DI + 255) / 256, 256>>>(out_proj_w, opwh, DM * DI);

    // 1) LayerNorm -> xn fp16
    ln_kernel<<<NTOK, 256>>>(x, norm_w, norm_b, xnh);

    // 2) in_proj: xz[4096,4096] = xn @ in_proj_w^T
    hmma_gemm<4, 0><<<dim3(XZC / 128, NTOK / 128), 256, gemm_smem(128)>>>(
        NTOK, XZC, DM, DM, xnh, w1h, xz, XZC, nullptr, nullptr, 0);

    // 3) conv + SiLU -> xconv f32 + fp16
    conv_silu_kernel<<<(NTOK * DI) / 256, 256>>>(xz, conv_w, conv_b, xconv, xch);

    // 4) x_proj (split-K x4): partials, then reduce (+ dt fp16)
    hmma_gemm<3, 0><<<dim3(1, NTOK / 128, XPS), 192, gemm_smem(96)>>>(
        NTOK, XDBC, DI, DI / XPS, xch, xpwh, xdbp, XDBC, nullptr, nullptr, 0);
    xdb_reduce_kernel<<<(NTOK * XDBC + 255) / 256, 256>>>(xdbp, xdb, dth);

    // 5) dt_proj + softplus: delta[4096,2048]
    hmma_gemm<4, 1><<<dim3(DI / 128, NTOK / 128), 256, gemm_smem(128)>>>(
        NTOK, DI, DTR, DTR, dth, dtwh, deltab, DI, dt_proj_b, nullptr, 0);

    // 6) selective scan -> ys fp16
    scan_kernel<<<32, 128, 2 * SCAN_TILEF * 4>>>(
        xconv, deltab, xz, xdb, A_log, D_param, ysh);

    // 7) out_proj + residual
    hmma_gemm<4, 2><<<dim3(DM / 128, NTOK / 128), 256, gemm_smem(128)>>>(
        NTOK, DM, DI, DI, ysh, opwh, out, DM, nullptr, x, DM);
}

// round 6
// speedup vs baseline: 9.2643x; 1.4809x over previous
#include <cuda_runtime.h>
#include <cuda_fp16.h>
#include <cstdint>
#include <math.h>

// ---------------------------------------------------------------------------
// Problem constants
// ---------------------------------------------------------------------------
#define DM    1024
#define DI    2048
#define DS    16
#define DTR   64
#define NB    2
#define LL    2048
#define NTOK  (NB*LL)       // 4096
#define XZC   (2*DI)        // 4096
#define XDBC  (DTR+2*DS)    // 96
#define XPS   4             // x_proj split-K factor
#define NCH   (NB*DI)       // 4096 scan channels
#define CL    128           // scan chunk length
#define NC    (LL/CL)       // 16 chunks

// ---------------------------------------------------------------------------
// Base-ISA helpers (sm_80+; no 'a'-gated instructions)
// ---------------------------------------------------------------------------
__device__ __forceinline__ uint32_t smem_u32(const void* p) {
    uint32_t a;
    asm("{ .reg .u64 t; cvta.to.shared.u64 t, %1; cvt.u32.u64 %0, t; }" : "=r"(a) : "l"(p));
    return a;
}
__device__ __forceinline__ void cp_async16(uint32_t sa, const void* gp) {
    asm volatile("cp.async.cg.shared.global [%0], [%1], 16;" :: "r"(sa), "l"(gp));
}
__device__ __forceinline__ void cp_commit() {
    asm volatile("cp.async.commit_group;" ::: "memory");
}
template<int N>
__device__ __forceinline__ void cp_wait() {
    asm volatile("cp.async.wait_group %0;" :: "n"(N) : "memory");
}
__device__ __forceinline__ void ldsm_x4(uint32_t* r, uint32_t addr) {
    asm volatile("ldmatrix.sync.aligned.m8n8.x4.shared.b16 {%0,%1,%2,%3}, [%4];"
        : "=r"(r[0]), "=r"(r[1]), "=r"(r[2]), "=r"(r[3]) : "r"(addr));
}
__device__ __forceinline__ void ldsm_x2(uint32_t* r, uint32_t addr) {
    asm volatile("ldmatrix.sync.aligned.m8n8.x2.shared.b16 {%0,%1}, [%2];"
        : "=r"(r[0]), "=r"(r[1]) : "r"(addr));
}
__device__ __forceinline__ void mma_fp16(float* c, const uint32_t* a, const uint32_t* b) {
    asm volatile("mma.sync.aligned.m16n8k16.row.col.f32.f16.f16.f32 "
        "{%0,%1,%2,%3},{%4,%5,%6,%7},{%8,%9},{%0,%1,%2,%3};"
        : "+f"(c[0]), "+f"(c[1]), "+f"(c[2]), "+f"(c[3])
        : "r"(a[0]), "r"(a[1]), "r"(a[2]), "r"(a[3]), "r"(b[0]), "r"(b[1]));
}
__device__ __forceinline__ float softplus_f(float v) {
    return (v > 20.f) ? v : log1pf(expf(v));
}
// dA powers: dA[n] = e^(n+1), e = exp(-dl) (fast path when A[n] = -(n+1))
__device__ __forceinline__ void dA_fast(float e, float* dA) {
    float e2 = e * e, e3 = e2 * e, e4 = e2 * e2, e8 = e4 * e4;
    dA[0] = e;        dA[1] = e2;       dA[2] = e3;       dA[3] = e4;
    dA[4] = e4 * e;   dA[5] = e4 * e2;  dA[6] = e4 * e3;  dA[7] = e8;
    dA[8] = e8 * e;   dA[9] = e8 * e2;  dA[10] = e8 * e3; dA[11] = e8 * e4;
    dA[12] = e8 * dA[4]; dA[13] = e8 * dA[5]; dA[14] = e8 * dA[6]; dA[15] = e8 * e8;
}

// ---------------------------------------------------------------------------
// Scratch (device globals)
// ---------------------------------------------------------------------------
__device__ __align__(16) __half g_xnh[(size_t)NTOK*DM];
__device__ __align__(16) __half g_w1h[(size_t)XZC*DM];
__device__ __align__(16) __half g_xz[(size_t)NTOK*XZC];         // fp16 now
__device__ __align__(16) float  g_xconv[(size_t)NTOK*DI];
__device__ __align__(16) __half g_xch[(size_t)NTOK*DI];
__device__ __align__(16) __half g_xpwh[(size_t)XDBC*DI];
__device__ __align__(16) float  g_xdbp[(size_t)XPS*NTOK*XDBC];
__device__ __align__(16) float  g_xdb[(size_t)NTOK*XDBC];
__device__ __align__(16) __half g_dth[(size_t)NTOK*DTR];
__device__ __align__(16) __half g_dtwh[(size_t)DI*DTR];
__device__ __align__(16) float  g_delta[(size_t)NTOK*DI];
__device__ __align__(16) __half g_ysh[(size_t)NTOK*DI];
__device__ __align__(16) __half g_opwh[(size_t)DM*DI];
__device__ __align__(16) float  g_q[(size_t)NC*NCH*DS];         // chunk-local end states
__device__ __align__(16) float  g_sumdl[(size_t)NC*NCH];        // per-chunk sum(delta)
__device__ __align__(16) float  g_hs[(size_t)NC*NCH*DS];        // chunk start states

// ---------------------------------------------------------------------------
// f32 -> fp16 convert
// ---------------------------------------------------------------------------
__global__ void whalf_kernel(const float* __restrict__ w, __half* __restrict__ h, int n)
{
    int i = blockIdx.x * 256 + threadIdx.x;
    if (i < n) h[i] = __float2half_rn(w[i]);
}

// ---------------------------------------------------------------------------
// LayerNorm -> fp16
// ---------------------------------------------------------------------------
__global__ void ln_kernel(const float* __restrict__ x, const float* __restrict__ w,
                          const float* __restrict__ bb, __half* __restrict__ oh)
{
    int t = blockIdx.x;
    const float* xr = x + (size_t)t * DM;
    float v[4];
    float s = 0.f, s2 = 0.f;
#pragma unroll
    for (int i = 0; i < 4; i++) {
        v[i] = xr[threadIdx.x + i * 256];
        s += v[i]; s2 += v[i] * v[i];
    }
#pragma unroll
    for (int o = 16; o > 0; o >>= 1) {
        s  += __shfl_xor_sync(0xffffffffu, s,  o);
        s2 += __shfl_xor_sync(0xffffffffu, s2, o);
    }
    __shared__ float rs[8], rs2[8];
    int wid = threadIdx.x >> 5, lid = threadIdx.x & 31;
    if (lid == 0) { rs[wid] = s; rs2[wid] = s2; }
    __syncthreads();
    if (wid == 0) {
        float a  = (lid < 8) ? rs[lid]  : 0.f;
        float a2 = (lid < 8) ? rs2[lid] : 0.f;
#pragma unroll
        for (int o = 4; o > 0; o >>= 1) {
            a  += __shfl_xor_sync(0xffffffffu, a,  o);
            a2 += __shfl_xor_sync(0xffffffffu, a2, o);
        }
        if (lid == 0) { rs[0] = a; rs2[0] = a2; }
    }
    __syncthreads();
    float mu = rs[0] * (1.f / DM);
    float var = rs2[0] * (1.f / DM) - mu * mu;
    float rstd = rsqrtf(var + 1e-5f);
#pragma unroll
    for (int i = 0; i < 4; i++) {
        int d = threadIdx.x + i * 256;
        float y = (v[i] - mu) * rstd * w[d] + bb[d];
        oh[(size_t)t * DM + d] = __float2half_rn(y);
    }
}

// ---------------------------------------------------------------------------
// fp16 HMMA GEMM: C[M,N] = A[M,K] @ B[N,K]^T, f32 accum.
// CTA 128 x BN (BN = NWN*32), warp tile 64x32, K-chunks of 64, cp.async
// double-buffered, SMEM rows 144 B (conflict-free ldmatrix). Optional split-K
// over gridDim.z. EPI: 0 plain f32, 1 softplus(+bias), 2 +resid, 4 fp16 out
// ---------------------------------------------------------------------------
template<int NWN, int EPI>
__global__ void __launch_bounds__(64 * NWN) hmma_gemm(
    int M, int N, int Ktot, int Kper,
    const __half* __restrict__ A, const __half* __restrict__ B,
    float* __restrict__ C, int ldc,
    const float* __restrict__ bias,
    const float* __restrict__ resid, int ldr)
{
    constexpr int BN      = NWN * 32;
    constexpr int THREADS = 64 * NWN;
    constexpr int RSTRIDE = 144;                // 64 fp16 (128B) + 16 pad
    constexpr int AB      = 128 * RSTRIDE;
    constexpr int BB      = BN * RSTRIDE;
    constexpr int BUF     = AB + BB;

    extern __shared__ char smraw[];
    const uint32_t sbase = smem_u32(smraw);

    const int tid  = threadIdx.x;
    const int lane = tid & 31;
    const int wid  = tid >> 5;
    const int warp_m = wid / NWN;
    const int warp_n = wid % NWN;
    const int bm = blockIdx.y * 128;
    const int bn = blockIdx.x * BN;
    const int kbase = blockIdx.z * Kper;
    const int KC = Kper >> 6;                   // chunks of 64
    float* Cz = C + (size_t)blockIdx.z * M * ldc;

    float acc[4][4][4];
#pragma unroll
    for (int i = 0; i < 4; i++)
#pragma unroll
        for (int j = 0; j < 4; j++)
#pragma unroll
            for (int q = 0; q < 4; q++) acc[i][j][q] = 0.f;

    auto load_chunk = [&](int c, int b) {
        const int koff = kbase + c * 64;
        const uint32_t bbase = sbase + (uint32_t)b * BUF;
        for (int i = tid; i < 1024; i += THREADS) {          // A: 128 rows x 8 segs
            int row = i >> 3, seg = i & 7;
            cp_async16(bbase + row * RSTRIDE + seg * 16,
                       A + (size_t)(bm + row) * Ktot + koff + seg * 8);
        }
        for (int i = tid; i < BN * 8; i += THREADS) {        // B: BN rows x 8 segs
            int row = i >> 3, seg = i & 7;
            cp_async16(bbase + AB + row * RSTRIDE + seg * 16,
                       B + (size_t)(bn + row) * Ktot + koff + seg * 8);
        }
        cp_commit();
    };

    load_chunk(0, 0);

    for (int c = 0; c < KC; c++) {
        const int b = c & 1;
        if (c + 1 < KC) { load_chunk(c + 1, (c + 1) & 1); cp_wait<1>(); }
        else            { cp_wait<0>(); }
        __syncthreads();

        const uint32_t bbase = sbase + (uint32_t)b * BUF;
#pragma unroll
        for (int ks = 0; ks < 4; ks++) {
            uint32_t ah[4][4], bh[4][2];
            const uint32_t a_lane = (uint32_t)((warp_m * 64 + (lane & 15)) * RSTRIDE
                                               + ks * 32 + (lane >> 4) * 16);
#pragma unroll
            for (int mi = 0; mi < 4; mi++)
                ldsm_x4(ah[mi], bbase + a_lane + mi * 16 * RSTRIDE);
            const int l16 = lane & 15;
            const uint32_t b_lane = (uint32_t)((warp_n * 32 + (l16 & 7)) * RSTRIDE
                                               + ks * 32 + (l16 >> 3) * 16);
#pragma unroll
            for (int ni = 0; ni < 4; ni++)
                ldsm_x2(bh[ni], bbase + AB + b_lane + ni * 8 * RSTRIDE);
#pragma unroll
            for (int mi = 0; mi < 4; mi++)
#pragma unroll
                for (int ni = 0; ni < 4; ni++)
                    mma_fp16(acc[mi][ni], ah[mi], bh[ni]);
        }
        __syncthreads();
    }

#pragma unroll
    for (int mi = 0; mi < 4; mi++)
#pragma unroll
        for (int ni = 0; ni < 4; ni++) {
            float* cc = acc[mi][ni];
            const int m0 = bm + warp_m * 64 + mi * 16 + (lane >> 2);
            const int n0 = bn + warp_n * 32 + ni * 8 + (lane & 3) * 2;
#pragma unroll
            for (int half = 0; half < 2; half++) {
                const int m = m0 + half * 8;
                float v0 = cc[half * 2], v1 = cc[half * 2 + 1];
                if (EPI == 1) { v0 = softplus_f(v0 + bias[n0]); v1 = softplus_f(v1 + bias[n0 + 1]); }
                if (EPI == 2) {
                    const float2 r2 = *(const float2*)(resid + (size_t)m * ldr + n0);
                    v0 += r2.x; v1 += r2.y;
                }
                if (EPI == 4) {
                    __half* Ch = (__half*)Cz;
                    *(__half2*)(Ch + (size_t)m * ldc + n0) = __floats2half2_rn(v0, v1);
                } else {
                    *(float2*)(Cz + (size_t)m * ldc + n0) = make_float2(v0, v1);
                }
            }
        }
}

// ---------------------------------------------------------------------------
// x_proj split-K reduce: xdb = sum_z partials; also emit dt (cols 0..63) fp16
// ---------------------------------------------------------------------------
__global__ void xdb_reduce_kernel(const float* __restrict__ part, float* __restrict__ xdb,
                                  __half* __restrict__ dth)
{
    int idx = blockIdx.x * 256 + threadIdx.x;
    if (idx >= NTOK * XDBC) return;
    float s = 0.f;
#pragma unroll
    for (int z = 0; z < XPS; z++) s += part[(size_t)z * NTOK * XDBC + idx];
    xdb[idx] = s;
    int n = idx % XDBC;
    if (n < DTR) {
        int m = idx / XDBC;
        dth[(size_t)m * DTR + n] = __float2half_rn(s);
    }
}

// ---------------------------------------------------------------------------
// Depthwise causal conv (k=4) + bias + SiLU; reads fp16 xz
// ---------------------------------------------------------------------------
__global__ void conv_silu_kernel(const __half* __restrict__ xz, const float* __restrict__ cw,
                                 const float* __restrict__ cb, float* __restrict__ out,
                                 __half* __restrict__ oh)
{
    int idx = blockIdx.x * blockDim.x + threadIdx.x;
    int d  = idx & (DI - 1);
    int bt = idx >> 11;
    int t  = bt & (LL - 1);
    int b  = bt >> 11;

    float w0 = cw[d * 4 + 0], w1 = cw[d * 4 + 1];
    float w2 = cw[d * 4 + 2], w3 = cw[d * 4 + 3];
    const __half* col = xz + (size_t)b * LL * XZC + d;
    float acc = cb[d];
    if (t >= 3) acc = fmaf(__half2float(col[(size_t)(t - 3) * XZC]), w0, acc);
    if (t >= 2) acc = fmaf(__half2float(col[(size_t)(t - 2) * XZC]), w1, acc);
    if (t >= 1) acc = fmaf(__half2float(col[(size_t)(t - 1) * XZC]), w2, acc);
    acc = fmaf(__half2float(col[(size_t)t * XZC]), w3, acc);
    float sig = __fdividef(1.f, 1.f + __expf(-acc));
    float r = acc * sig;
    out[(size_t)bt * DI + d] = r;
    oh[(size_t)bt * DI + d] = __float2half_rn(r);
}

// ---------------------------------------------------------------------------
// Chunked scan, phase A: per chunk, local scan with h0=0 -> q, sum(delta).
// grid 512 = tc(16) x [b(2) x dchunk(16)], 128 threads (one channel each).
// ---------------------------------------------------------------------------
__global__ void __launch_bounds__(128) scanA_kernel(
    const float* __restrict__ delta, const float* __restrict__ u,
    const float* __restrict__ xdb, const float* __restrict__ A_log,
    float* __restrict__ q, float* __restrict__ sumdl)
{
    const int tc = blockIdx.x & 15;
    const int g  = blockIdx.x >> 4;
    const int b  = g >> 4;
    const int d0 = (g & 15) << 7;
    const int tid = threadIdx.x;
    const int d = d0 + tid;

    float An[DS];
    bool fast = true;
#pragma unroll
    for (int n = 0; n < DS; n++) {
        An[n] = -expf(A_log[d * DS + n]);
        fast = fast && (fabsf(An[n] + (float)(n + 1)) < 1e-4f * (float)(n + 1));
    }
    float h[DS];
#pragma unroll
    for (int n = 0; n < DS; n++) h[n] = 0.f;
    float sdl = 0.f;

    const size_t base_u  = (size_t)b * LL * DI + d0 + tid;
    const size_t base_bc = (size_t)b * LL * XDBC + DTR;
    const int t0 = tc * CL;

    __shared__ float sB[32][DS];
    for (int tile = 0; tile < CL / 32; tile++) {
        __syncthreads();
        for (int i = tid; i < 32 * DS; i += 128) {
            int s = i >> 4, j = i & 15;
            sB[s][j] = xdb[base_bc + (size_t)(t0 + tile * 32 + s) * XDBC + j];
        }
        __syncthreads();
#pragma unroll 2
        for (int s = 0; s < 32; s++) {
            const int t = t0 + tile * 32 + s;
            float dl = delta[base_u + (size_t)t * DI];
            float ut = u[base_u + (size_t)t * DI];
            sdl += dl;
            float dA[DS];
            if (fast) { dA_fast(__expf(-dl), dA); }
            else {
#pragma unroll
                for (int n = 0; n < DS; n++) dA[n] = __expf(dl * An[n]);
            }
            float w = dl * ut;
#pragma unroll
            for (int n = 0; n < DS; n++)
                h[n] = fmaf(dA[n], h[n], w * sB[s][n]);
        }
    }
    const int bd = b * DI + d;
    float* qp = q + ((size_t)tc * NCH + bd) * DS;
#pragma unroll
    for (int n = 0; n < DS; n += 4)
        *(float4*)(qp + n) = make_float4(h[n], h[n + 1], h[n + 2], h[n + 3]);
    sumdl[tc * NCH + bd] = sdl;
}

// ---------------------------------------------------------------------------
// Chunked scan, phase B: serial prefix over 16 chunks -> h_start per chunk.
// ---------------------------------------------------------------------------
__global__ void __launch_bounds__(128) scanB_kernel(
    const float* __restrict__ q, const float* __restrict__ sumdl,
    const float* __restrict__ A_log, float* __restrict__ hs)
{
    const int bd = blockIdx.x * 128 + threadIdx.x;
    const int d = bd & (DI - 1);

    float An[DS];
    bool fast = true;
#pragma unroll
    for (int n = 0; n < DS; n++) {
        An[n] = -expf(A_log[d * DS + n]);
        fast = fast && (fabsf(An[n] + (float)(n + 1)) < 1e-4f * (float)(n + 1));
    }
    float h[DS];
#pragma unroll
    for (int n = 0; n < DS; n++) h[n] = 0.f;

    for (int c = 0; c < NC; c++) {
        float* hp = hs + ((size_t)c * NCH + bd) * DS;
#pragma unroll
        for (int n = 0; n < DS; n += 4)
            *(float4*)(hp + n) = make_float4(h[n], h[n + 1], h[n + 2], h[n + 3]);
        if (c == NC - 1) break;
        float sdl = sumdl[c * NCH + bd];
        float P[DS];
        if (fast) { dA_fast(__expf(-sdl), P); }
        else {
#pragma unroll
            for (int n = 0; n < DS; n++) P[n] = __expf(An[n] * sdl);
        }
        const float* qp = q + ((size_t)c * NCH + bd) * DS;
#pragma unroll
        for (int n = 0; n < DS; n++)
            h[n] = fmaf(P[n], h[n], qp[n]);
    }
}

// ---------------------------------------------------------------------------
// Chunked scan, phase C: re-scan with correct h_start, gate with silu(z),
// write ys fp16.
// ---------------------------------------------------------------------------
__global__ void __launch_bounds__(128) scanC_kernel(
    const float* __restrict__ delta, const float* __restrict__ u,
    const __half* __restrict__ xz, const float* __restrict__ xdb,
    const float* __restrict__ A_log, const float* __restrict__ Dp,
    const float* __restrict__ hs, __half* __restrict__ ysh)
{
    const int tc = blockIdx.x & 15;
    const int g  = blockIdx.x >> 4;
    const int b  = g >> 4;
    const int d0 = (g & 15) << 7;
    const int tid = threadIdx.x;
    const int d = d0 + tid;

    float An[DS];
    bool fast = true;
#pragma unroll
    for (int n = 0; n < DS; n++) {
        An[n] = -expf(A_log[d * DS + n]);
        fast = fast && (fabsf(An[n] + (float)(n + 1)) < 1e-4f * (float)(n + 1));
    }
    float Dd = Dp[d];
    const int bd = b * DI + d;
    float h[DS];
    {
        const float* hp = hs + ((size_t)tc * NCH + bd) * DS;
#pragma unroll
        for (int n = 0; n < DS; n += 4) {
            float4 v = *(const float4*)(hp + n);
            h[n] = v.x; h[n + 1] = v.y; h[n + 2] = v.z; h[n + 3] = v.w;
        }
    }

    const size_t base_u  = (size_t)b * LL * DI + d0 + tid;
    const size_t base_z  = (size_t)b * LL * XZC + DI + d0 + tid;
    const size_t base_bc = (size_t)b * LL * XDBC + DTR;
    const int t0 = tc * CL;

    __shared__ float sBC[32][2 * DS];
    for (int tile = 0; tile < CL / 32; tile++) {
        __syncthreads();
        for (int i = tid; i < 32 * 2 * DS; i += 128) {
            int s = i >> 5, j = i & 31;
            sBC[s][j] = xdb[base_bc + (size_t)(t0 + tile * 32 + s) * XDBC + j];
        }
        __syncthreads();
#pragma unroll 2
        for (int s = 0; s < 32; s++) {
            const int t = t0 + tile * 32 + s;
            float dl = delta[base_u + (size_t)t * DI];
            float ut = u[base_u + (size_t)t * DI];
            float zt = __half2float(xz[base_z + (size_t)t * XZC]);
            float dA[DS];
            if (fast) { dA_fast(__expf(-dl), dA); }
            else {
#pragma unroll
                for (int n = 0; n < DS; n++) dA[n] = __expf(dl * An[n]);
            }
            float w = dl * ut;
#pragma unroll
            for (int n = 0; n < DS; n++)
                h[n] = fmaf(dA[n], h[n], w * sBC[s][n]);

            float y0 = 0.f, y1 = 0.f, y2 = 0.f, y3 = 0.f;
#pragma unroll
            for (int n = 0; n < DS; n += 4) {
                y0 = fmaf(h[n],     sBC[s][DS + n],     y0);
                y1 = fmaf(h[n + 1], sBC[s][DS + n + 1], y1);
                y2 = fmaf(h[n + 2], sBC[s][DS + n + 2], y2);
                y3 = fmaf(h[n + 3], sBC[s][DS + n + 3], y3);
            }
            float y = (y0 + y1) + (y2 + y3) + ut * Dd;
            float sig = __fdividef(1.f, 1.f + __expf(-zt));
            ysh[base_u + (size_t)t * DI] = __float2half_rn(y * zt * sig);
        }
    }
}

// ---------------------------------------------------------------------------
// Launch sequence
// ---------------------------------------------------------------------------
static inline int gemm_smem(int BN) { return 2 * (128 + BN) * 144; }

extern "C" void kernel_launch(void* const* d_in, const int* in_sizes, int n_in,
                              void* d_out, int out_size)
{
    const float* x         = (const float*)d_in[0];
    const float* norm_w    = (const float*)d_in[1];
    const float* norm_b    = (const float*)d_in[2];
    const float* in_proj_w = (const float*)d_in[3];
    const float* conv_w    = (const float*)d_in[4];
    const float* conv_b    = (const float*)d_in[5];
    const float* x_proj_w  = (const float*)d_in[6];
    const float* dt_proj_w = (const float*)d_in[7];
    const float* dt_proj_b = (const float*)d_in[8];
    const float* A_log     = (const float*)d_in[9];
    const float* D_param   = (const float*)d_in[10];
    const float* out_proj_w= (const float*)d_in[11];
    float* out = (float*)d_out;

    __half *xnh, *w1h, *xzh, *xch, *xpwh, *dth, *dtwh, *ysh, *opwh;
    float *xconv, *xdbp, *xdb, *deltab, *qb, *sumdlb, *hsb;
    cudaGetSymbolAddress((void**)&xnh, g_xnh);
    cudaGetSymbolAddress((void**)&w1h, g_w1h);
    cudaGetSymbolAddress((void**)&xzh, g_xz);
    cudaGetSymbolAddress((void**)&xconv, g_xconv);
    cudaGetSymbolAddress((void**)&xch, g_xch);
    cudaGetSymbolAddress((void**)&xpwh, g_xpwh);
    cudaGetSymbolAddress((void**)&xdbp, g_xdbp);
    cudaGetSymbolAddress((void**)&xdb, g_xdb);
    cudaGetSymbolAddress((void**)&dth, g_dth);
    cudaGetSymbolAddress((void**)&dtwh, g_dtwh);
    cudaGetSymbolAddress((void**)&deltab, g_delta);
    cudaGetSymbolAddress((void**)&ysh, g_ysh);
    cudaGetSymbolAddress((void**)&opwh, g_opwh);
    cudaGetSymbolAddress((void**)&qb, g_q);
    cudaGetSymbolAddress((void**)&sumdlb, g_sumdl);
    cudaGetSymbolAddress((void**)&hsb, g_hs);

    cudaFuncSetAttribute(hmma_gemm<4, 4>, cudaFuncAttributeMaxDynamicSharedMemorySize, gemm_smem(128));
    cudaFuncSetAttribute(hmma_gemm<4, 1>, cudaFuncAttributeMaxDynamicSharedMemorySize, gemm_smem(128));
    cudaFuncSetAttribute(hmma_gemm<4, 2>, cudaFuncAttributeMaxDynamicSharedMemorySize, gemm_smem(128));
    cudaFuncSetAttribute(hmma_gemm<3, 0>, cudaFuncAttributeMaxDynamicSharedMemorySize, gemm_smem(96));

    // weight converts
    whalf_kernel<<<(XZC * DM + 255) / 256, 256>>>(in_proj_w, w1h, XZC * DM);
    whalf_kernel<<<(XDBC * DI + 255) / 256, 256>>>(x_proj_w, xpwh, XDBC * DI);
    whalf_kernel<<<(DI * DTR + 255) / 256, 256>>>(dt_proj_w, dtwh, DI * DTR);
    whalf_kernel<<<(DM * DI + 255) / 256, 256>>>(out_proj_w, opwh, DM * DI);

    // 1) LayerNorm -> xn fp16
    ln_kernel<<<NTOK, 256>>>(x, norm_w, norm_b, xnh);

    // 2) in_proj: xz(fp16)[4096,4096] = xn @ in_proj_w^T
    hmma_gemm<4, 4><<<dim3(XZC / 128, NTOK / 128), 256, gemm_smem(128)>>>(
        NTOK, XZC, DM, DM, xnh, w1h, (float*)xzh, XZC, nullptr, nullptr, 0);

    // 3) conv + SiLU -> xconv f32 + fp16
    conv_silu_kernel<<<(NTOK * DI) / 256, 256>>>(xzh, conv_w, conv_b, xconv, xch);

    // 4) x_proj (split-K x4): partials, then reduce (+ dt fp16)
    hmma_gemm<3, 0><<<dim3(1, NTOK / 128, XPS), 192, gemm_smem(96)>>>(
        NTOK, XDBC, DI, DI / XPS, xch, xpwh, xdbp, XDBC, nullptr, nullptr, 0);
    xdb_reduce_kernel<<<(NTOK * XDBC + 255) / 256, 256>>>(xdbp, xdb, dth);

    // 5) dt_proj + softplus: delta[4096,2048]
    hmma_gemm<4, 1><<<dim3(DI / 128, NTOK / 128), 256, gemm_smem(128)>>>(
        NTOK, DI, DTR, DTR, dth, dtwh, deltab, DI, dt_proj_b, nullptr, 0);

    // 6) chunked selective scan -> ys fp16
    scanA_kernel<<<NC * 32, 128>>>(deltab, xconv, xdb, A_log, qb, sumdlb);
    scanB_kernel<<<NCH / 128, 128>>>(qb, sumdlb, A_log, hsb);
    scanC_kernel<<<NC * 32, 128>>>(deltab, xconv, xzh, xdb, A_log, D_param, hsb, ysh);

    // 7) out_proj + residual
    hmma_gemm<4, 2><<<dim3(DM / 128, NTOK / 128), 256, gemm_smem(128)>>>(
        NTOK, DM, DI, DI, ysh, opwh, out, DM, nullptr, x, DM);
}